// round 10
// baseline (speedup 1.0000x reference)
#include <cuda_runtime.h>
#include <cuda_bf16.h>
#include <math.h>
#include <stdint.h>

#define D_DIM 256
#define MAXB  64
#define MAXK  4096
#define TOPK_NT 1024
#define SEG   20
#define WSPLIT_BLOCKS 16

#define MT    128                 // tokens per GEMM block
#define KC    64                  // K elements per chunk
#define NCHUNK (D_DIM / KC)       // 4
// dynamic smem layout (bytes): A double buf then B double buf, 128B rows, XOR swizzle
#define A_HALF  16384             // 128 rows * 128 B (one precision)
#define A_BUF   (2 * A_HALF)      // hi + lo
#define B_HALF  32768             // 256 rows * 128 B
#define B_BUF   (2 * B_HALF)
#define OFF_B   (2 * A_BUF)       // 65536
#define DYN_BYTES (2 * A_BUF + 2 * B_BUF)   // 196608

// scratch (no cudaMalloc allowed)
__device__ int g_sel[MAXB * MAXK];
__device__ int g_cnt[MAXB];
__device__ __nv_bfloat16 g_w2hi[D_DIM * D_DIM];
__device__ __nv_bfloat16 g_w2lo[D_DIM * D_DIM];

// ---------------- mma / ldmatrix / cp.async helpers ----------------
__device__ __forceinline__ void mma_bf16(float* c, const uint32_t* a, const uint32_t* b) {
    asm volatile(
        "mma.sync.aligned.m16n8k16.row.col.f32.bf16.bf16.f32 "
        "{%0,%1,%2,%3}, {%4,%5,%6,%7}, {%8,%9}, {%0,%1,%2,%3};"
        : "+f"(c[0]), "+f"(c[1]), "+f"(c[2]), "+f"(c[3])
        : "r"(a[0]), "r"(a[1]), "r"(a[2]), "r"(a[3]), "r"(b[0]), "r"(b[1]));
}
__device__ __forceinline__ void ldm_x4(uint32_t* r, const char* p) {
    uint32_t a = (uint32_t)__cvta_generic_to_shared(p);
    asm volatile("ldmatrix.sync.aligned.m8n8.x4.shared.b16 {%0,%1,%2,%3}, [%4];"
                 : "=r"(r[0]), "=r"(r[1]), "=r"(r[2]), "=r"(r[3]) : "r"(a));
}
__device__ __forceinline__ void cpa16(char* dst, const void* src) {
    uint32_t s = (uint32_t)__cvta_generic_to_shared(dst);
    asm volatile("cp.async.cg.shared.global [%0], [%1], 16;" :: "r"(s), "l"(src));
}
__device__ __forceinline__ void cpa_commit() {
    asm volatile("cp.async.commit_group;" ::: "memory");
}
__device__ __forceinline__ void cpa_wait0() {
    asm volatile("cp.async.wait_group 0;" ::: "memory");
}

// ---------------- block scan (exclusive) ----------------
__device__ __forceinline__ void block_scan(int v, int& excl, int& total) {
    const int tid  = threadIdx.x;
    const int lane = tid & 31, wrp = tid >> 5;
    const int nw   = blockDim.x >> 5;
    __shared__ int wsum[32];
    int inc = v;
#pragma unroll
    for (int o = 1; o < 32; o <<= 1) {
        int n = __shfl_up_sync(0xFFFFFFFFu, inc, o);
        if (lane >= o) inc += n;
    }
    if (lane == 31) wsum[wrp] = inc;
    __syncthreads();
    if (wrp == 0) {
        int w = (lane < nw) ? wsum[lane] : 0;
#pragma unroll
        for (int o = 1; o < 32; o <<= 1) {
            int n = __shfl_up_sync(0xFFFFFFFFu, w, o);
            if (lane >= o) w += n;
        }
        wsum[lane] = w;
    }
    __syncthreads();
    int woff = wrp ? wsum[wrp - 1] : 0;
    excl  = woff + inc - v;
    total = wsum[nw - 1];
    __syncthreads();
}

// ---------------- fused: top-k + cls/mask epilogue + w2 hi/lo split ----------------
__global__ __launch_bounds__(TOPK_NT)
void topk_kernel(const float* __restrict__ expr,
                 const float* __restrict__ w2,
                 const float* __restrict__ cls,
                 float* __restrict__ out,
                 int B, int G, int K, int hasMask) {
    const int tid = threadIdx.x;

    if (blockIdx.x >= (unsigned)B) {
        // ---- w2 split path: 16 blocks x 1024 threads x 4 elems ----
        int idx = ((blockIdx.x - B) * TOPK_NT + tid) * 4;
        if (idx < D_DIM * D_DIM) {
            float4 w = *(const float4*)(&w2[idx]);
            float wv[4] = {w.x, w.y, w.z, w.w};
            uint32_t hpack[2], lpack[2];
            unsigned short hs[4], ls[4];
#pragma unroll
            for (int j = 0; j < 4; ++j) {
                __nv_bfloat16 hi = __float2bfloat16(wv[j]);
                float lo_f = wv[j] - __bfloat162float(hi);
                __nv_bfloat16 lo = __float2bfloat16(lo_f);
                hs[j] = *(unsigned short*)&hi;
                ls[j] = *(unsigned short*)&lo;
            }
            hpack[0] = hs[0] | ((uint32_t)hs[1] << 16);
            hpack[1] = hs[2] | ((uint32_t)hs[3] << 16);
            lpack[0] = ls[0] | ((uint32_t)ls[1] << 16);
            lpack[1] = ls[2] | ((uint32_t)ls[3] << 16);
            *(uint2*)(&g_w2hi[idx]) = make_uint2(hpack[0], hpack[1]);
            *(uint2*)(&g_w2lo[idx]) = make_uint2(lpack[0], lpack[1]);
        }
        return;
    }

    const int b = blockIdx.x;
    const float* __restrict__ row = expr + (size_t)b * G;

    __shared__ unsigned int hist[256];
    __shared__ unsigned int s_prefix;
    __shared__ int s_remaining;

    const int base = tid * SEG;
    unsigned keys[SEG];
    if (base + SEG <= G) {
#pragma unroll
        for (int i = 0; i < SEG; i += 4) {
            float4 v = *(const float4*)(&row[base + i]);
            keys[i + 0] = __float_as_uint(v.x);
            keys[i + 1] = __float_as_uint(v.y);
            keys[i + 2] = __float_as_uint(v.z);
            keys[i + 3] = __float_as_uint(v.w);
        }
    } else {
#pragma unroll
        for (int i = 0; i < SEG; ++i)
            keys[i] = (base + i < G) ? __float_as_uint(row[base + i]) : 0u;
    }

    if (tid == 0) { s_prefix = 0u; s_remaining = K; }
    __syncthreads();

#pragma unroll
    for (int pass = 0; pass < 4; ++pass) {
        const int shift = 24 - 8 * pass;
        const unsigned maskHigh = (pass == 0) ? 0u : (0xFFFFFFFFu << (shift + 8));
        if (tid < 256) hist[tid] = 0u;
        __syncthreads();
        const unsigned prefix = s_prefix;
        const int rem = s_remaining;
#pragma unroll
        for (int i = 0; i < SEG; ++i) {
            unsigned key = keys[i];
            if ((key & maskHigh) == prefix)
                atomicAdd(&hist[(key >> shift) & 0xFFu], 1u);
        }
        __syncthreads();
        int v = (tid < 256) ? (int)hist[255 - tid] : 0;
        int excl, total;
        block_scan(v, excl, total);
        int incl = excl + v;
        if (tid < 256 && incl >= rem && excl < rem) {
            s_prefix    = prefix | ((unsigned)(255 - tid) << shift);
            s_remaining = rem - excl;
        }
        __syncthreads();
    }
    const unsigned pivot = s_prefix;
    const int r = s_remaining;

    int n_gt = 0, n_eq = 0;
#pragma unroll
    for (int i = 0; i < SEG; ++i) {
        n_gt += (keys[i] > pivot);
        n_eq += (keys[i] == pivot);
    }
    int eq_base, eq_tot;
    block_scan(n_eq, eq_base, eq_tot);
    int eq_keep = 0;
    if (pivot > 0u) {
        int take = r - eq_base;
        eq_keep = take < 0 ? 0 : (take > n_eq ? n_eq : take);
    }
    int n_keep = n_gt + eq_keep;
    int out_base, out_tot;
    block_scan(n_keep, out_base, out_tot);

    int pos = out_base, erank = eq_base;
    int* __restrict__ sel = g_sel + b * MAXK;
#pragma unroll
    for (int i = 0; i < SEG; ++i) {
        unsigned key = keys[i];
        if (key > pivot) {
            sel[pos++] = base + i;
        } else if (key == pivot) {
            if (pivot > 0u && erank < r) sel[pos++] = base + i;
            ++erank;
        }
    }
    const int cnt = (out_tot < K) ? out_tot : K;
    if (tid == 0) g_cnt[b] = cnt;

    // ---- fused cls row + mask epilogue ----
    const size_t rowsz = (size_t)(K + 1) * D_DIM;
    float* orow = out + (size_t)b * rowsz;
    if (tid < D_DIM) orow[tid] = cls[tid];
    if (hasMask) {
        float* mask = out + (size_t)B * rowsz + (size_t)b * (K + 1);
        for (int j = tid; j < K + 1; j += TOPK_NT)
            mask[j] = (j == 0 || (j - 1) < cnt) ? 1.0f : 0.0f;
    }
}

// ---------------- token GEMM via mma.sync bf16 (3-pass hi/lo, pipelined) ----------------
// Block: 256 threads = 8 warps (2 x 4). Block tile 128 tokens x 256 outputs.
// Warp tile: 64 tokens x 64 outputs (mi=4, ni=8). K = 256 in 4 chunks of 64.
// Swizzled smem (128B rows, off ^= (row&7)<<4), cp.async.cg B fills, 2-stage pipeline.
__global__ __launch_bounds__(256, 1)
void gemm_kernel(const float* __restrict__ expr,
                 const float* __restrict__ gene_emb,
                 const float* __restrict__ w1,
                 const float* __restrict__ b1,
                 const float* __restrict__ b2,
                 float* __restrict__ out,
                 int B, int G, int K) {
    extern __shared__ char dyn[];

    __shared__ float sx[MT];
    __shared__ int   sgm[MT];
    __shared__ float sw1[D_DIM], sb1[D_DIM], sb2[D_DIM];

    const int tid  = threadIdx.x;
    const int wid  = tid >> 5, lane = tid & 31;
    const int wm   = wid >> 2;            // 0..1 (token dim, 64 each)
    const int wn   = wid & 3;             // 0..3 (output dim, 64 each)
    const int gr   = lane >> 2;           // 0..7
    const int cq   = lane & 3;            // 0..3
    const int t0   = blockIdx.x * MT;
    const int bb   = t0 / K;              // K % MT == 0

    if (tid < MT) {
        int k = t0 - bb * K + tid;
        int g = -1; float x = 0.0f;
        if (bb < B && k < g_cnt[bb]) {
            g = g_sel[bb * MAXK + k];
            x = expr[(size_t)bb * G + g];
        }
        sgm[tid] = g; sx[tid] = x;
    }
    if (tid < D_DIM) { sw1[tid] = w1[tid]; sb1[tid] = b1[tid]; sb2[tid] = b2[tid]; }
    __syncthreads();

    float acc[4][8][4];
#pragma unroll
    for (int mi = 0; mi < 4; ++mi)
#pragma unroll
        for (int ni = 0; ni < 8; ++ni)
#pragma unroll
            for (int j = 0; j < 4; ++j) acc[mi][ni][j] = 0.0f;

    // per-thread fill constants
    const int at  = tid >> 1;             // token row 0..127 for A fill
    const int kh  = (tid & 1) * 32;       // k offset base for A fill
    const float ax = sx[at];
    const uint32_t a_fill_base = (uint32_t)(at * 128);
    const uint32_t a_fill_x    = (uint32_t)((at & 7) << 4);
    const int bn0 = tid >> 3;             // 0..31 B fill row base
    const int bk16 = tid & 7;             // 16B group

    // per-thread ldmatrix constants
    const int a_r   = (lane & 7) + ((lane >> 3) & 1) * 8;   // row-in-16 for A tiles
    const uint32_t a_kb4 = (uint32_t)((lane >> 4) << 4);    // k 16B-group bit
    const int b_r   = (lane & 7) + ((lane >> 4) & 1) * 8;
    const uint32_t b_kb4 = (uint32_t)(((lane >> 3) & 1) << 4);
    const uint32_t xo = (uint32_t)((lane & 7) << 4);        // swizzle xor (row&7)<<4

    // ---- fill helpers as lambdas ----
    auto fillB = [&](int c, int buf) {
        char* Bh = dyn + OFF_B + buf * B_BUF;
        char* Bl = Bh + B_HALF;
        const int d0 = c * KC;
#pragma unroll
        for (int i = 0; i < 8; ++i) {
            int n = bn0 + 32 * i;
            uint32_t doff = (uint32_t)(n * 128) + (((uint32_t)(bk16 * 16)) ^ ((uint32_t)((n & 7) << 4)));
            const __nv_bfloat16* sh = &g_w2hi[(size_t)n * D_DIM + d0 + bk16 * 8];
            const __nv_bfloat16* sl = &g_w2lo[(size_t)n * D_DIM + d0 + bk16 * 8];
            cpa16(Bh + doff, sh);
            cpa16(Bl + doff, sl);
        }
        cpa_commit();
    };
    auto fillA = [&](int c, int buf) {
        char* Ah = dyn + buf * A_BUF;
        char* Al = Ah + A_HALF;
        const int d0 = c * KC;
#pragma unroll
        for (int j = 0; j < 16; ++j) {
            int kk = kh + 2 * j;
            int d  = d0 + kk;
            float z0 = fmaf(ax, sw1[d], sb1[d]);
            float z1 = fmaf(ax, sw1[d + 1], sb1[d + 1]);
            float h0 = 0.5f * z0 * (1.0f + erff(z0 * 0.70710678118654752f));
            float h1 = 0.5f * z1 * (1.0f + erff(z1 * 0.70710678118654752f));
            __nv_bfloat16 hi0 = __float2bfloat16(h0);
            __nv_bfloat16 hi1 = __float2bfloat16(h1);
            __nv_bfloat16 lo0 = __float2bfloat16(h0 - __bfloat162float(hi0));
            __nv_bfloat16 lo1 = __float2bfloat16(h1 - __bfloat162float(hi1));
            uint32_t hp = (uint32_t)*(unsigned short*)&hi0 | ((uint32_t)*(unsigned short*)&hi1 << 16);
            uint32_t lp = (uint32_t)*(unsigned short*)&lo0 | ((uint32_t)*(unsigned short*)&lo1 << 16);
            uint32_t boff = a_fill_base + (((uint32_t)(2 * kk)) ^ a_fill_x);
            *(uint32_t*)(Ah + boff) = hp;
            *(uint32_t*)(Al + boff) = lp;
        }
    };

    // ---- prologue: stage chunk 0 ----
    fillB(0, 0);
    fillA(0, 0);
    cpa_wait0();
    __syncthreads();

    for (int c = 0; c < NCHUNK; ++c) {
        const int cur = c & 1, nxt = cur ^ 1;
        if (c < NCHUNK - 1) { fillB(c + 1, nxt); fillA(c + 1, nxt); }

        char* Ah = dyn + cur * A_BUF;
        char* Al = Ah + A_HALF;
        char* Bh = dyn + OFF_B + cur * B_BUF;
        char* Bl = Bh + B_HALF;

#pragma unroll
        for (int ks = 0; ks < 4; ++ks) {
            const uint32_t kb2 = (uint32_t)(ks * 32);
            const uint32_t aks = (kb2 | a_kb4) ^ xo;
            const uint32_t bks = (kb2 | b_kb4) ^ xo;
            uint32_t ahi[4][4], alo[4][4];
#pragma unroll
            for (int mi = 0; mi < 4; ++mi) {
                const uint32_t aoff = (uint32_t)((wm * 64 + mi * 16 + a_r) * 128) + aks;
                ldm_x4(ahi[mi], Ah + aoff);
                ldm_x4(alo[mi], Al + aoff);
            }
#pragma unroll
            for (int p = 0; p < 4; ++p) {
                const uint32_t boff = (uint32_t)((wn * 64 + p * 16 + b_r) * 128) + bks;
                uint32_t bh[4], bl[4];
                ldm_x4(bh, Bh + boff);
                ldm_x4(bl, Bl + boff);
#pragma unroll
                for (int half = 0; half < 2; ++half) {
                    const int ni = p * 2 + half;
                    const uint32_t* bhv = bh + half * 2;
                    const uint32_t* blv = bl + half * 2;
#pragma unroll
                    for (int mi = 0; mi < 4; ++mi) {
                        mma_bf16(acc[mi][ni], ahi[mi], bhv);
                        mma_bf16(acc[mi][ni], ahi[mi], blv);
                        mma_bf16(acc[mi][ni], alo[mi], bhv);
                    }
                }
            }
        }
        if (c < NCHUNK - 1) cpa_wait0();
        __syncthreads();
    }

    // ---------------- epilogue ----------------
#pragma unroll
    for (int mi = 0; mi < 4; ++mi) {
#pragma unroll
        for (int half = 0; half < 2; ++half) {
            int t_local = wm * 64 + mi * 16 + gr + half * 8;
            int g = sgm[t_local];
            int k_in = t0 + t_local - bb * K;
            size_t rowoff = ((size_t)bb * (K + 1) + (k_in + 1)) * D_DIM;
#pragma unroll
            for (int ni = 0; ni < 8; ++ni) {
                int e = wn * 64 + ni * 8 + 2 * cq;
                float c0 = acc[mi][ni][half * 2 + 0];
                float c1 = acc[mi][ni][half * 2 + 1];
                float2 v;
                if (g >= 0) {
                    float2 ge = *(const float2*)(&gene_emb[(size_t)g * D_DIM + e]);
                    v.x = c0 + ge.x + sb2[e + 0];
                    v.y = c1 + ge.y + sb2[e + 1];
                } else {
                    v = make_float2(0.f, 0.f);
                }
                *(float2*)(&out[rowoff + e]) = v;
            }
        }
    }
}

extern "C" void kernel_launch(void* const* d_in, const int* in_sizes, int n_in,
                              void* d_out, int out_size) {
    const float* expr     = (const float*)d_in[0];
    const float* gene_emb = (const float*)d_in[1];
    const float* w1       = (const float*)d_in[2];
    const float* b1       = (const float*)d_in[3];
    const float* w2       = (const float*)d_in[4];
    const float* b2       = (const float*)d_in[5];
    const float* cls      = (const float*)d_in[6];
    float* out = (float*)d_out;

    const int D = in_sizes[2];              // 256
    const int G = in_sizes[1] / D;          // 20000
    const int B = in_sizes[0] / G;          // 16

    long Kp1; int hasMask;
    if (out_size % ((long)B * (D + 1)) == 0) {
        Kp1 = out_size / ((long)B * (D + 1));
        hasMask = 1;
    } else {
        Kp1 = out_size / ((long)B * D);
        hasMask = 0;
    }
    const int K = (int)Kp1 - 1;             // 2048
    if (B > MAXB || K > MAXK || D != D_DIM) return;
    if (TOPK_NT * SEG < G) return;
    if (K % MT != 0) return;

    cudaFuncSetAttribute(gemm_kernel,
                         cudaFuncAttributeMaxDynamicSharedMemorySize, DYN_BYTES);

    topk_kernel<<<B + WSPLIT_BLOCKS, TOPK_NT>>>(expr, w2, cls, out, B, G, K, hasMask);

    int tiles = (B * K) / MT;               // 256
    gemm_kernel<<<tiles, 256, DYN_BYTES>>>(expr, gene_emb, w1, b1, b2, out, B, G, K);
}

// round 11
// speedup vs baseline: 1.0907x; 1.0907x over previous
#include <cuda_runtime.h>
#include <cuda_bf16.h>
#include <math.h>
#include <stdint.h>

#define D_DIM 256
#define MAXB  64
#define MAXK  4096
#define TOPK_NT 1024
#define SEG   20
#define WSPLIT_BLOCKS 16

#define MT    128                 // tokens per GEMM block
#define KC    64                  // K elements per chunk
#define NCHUNK (D_DIM / KC)       // 4
#define GEMM_NT 512               // 16 warps
// dynamic smem layout (bytes): A double buf then B double buf, 128B rows, XOR swizzle
#define A_HALF  16384             // 128 rows * 128 B (one precision)
#define A_BUF   (2 * A_HALF)      // hi + lo
#define B_HALF  32768             // 256 rows * 128 B
#define B_BUF   (2 * B_HALF)
#define OFF_B   (2 * A_BUF)       // 65536
#define DYN_BYTES (2 * A_BUF + 2 * B_BUF)   // 196608

// scratch (no cudaMalloc allowed)
__device__ int g_sel[MAXB * MAXK];
__device__ int g_cnt[MAXB];
__device__ __nv_bfloat16 g_w2hi[D_DIM * D_DIM];
__device__ __nv_bfloat16 g_w2lo[D_DIM * D_DIM];

// ---------------- mma / ldmatrix / cp.async helpers ----------------
__device__ __forceinline__ void mma_bf16(float* c, const uint32_t* a, const uint32_t* b) {
    asm volatile(
        "mma.sync.aligned.m16n8k16.row.col.f32.bf16.bf16.f32 "
        "{%0,%1,%2,%3}, {%4,%5,%6,%7}, {%8,%9}, {%0,%1,%2,%3};"
        : "+f"(c[0]), "+f"(c[1]), "+f"(c[2]), "+f"(c[3])
        : "r"(a[0]), "r"(a[1]), "r"(a[2]), "r"(a[3]), "r"(b[0]), "r"(b[1]));
}
__device__ __forceinline__ void ldm_x4(uint32_t* r, const char* p) {
    uint32_t a = (uint32_t)__cvta_generic_to_shared(p);
    asm volatile("ldmatrix.sync.aligned.m8n8.x4.shared.b16 {%0,%1,%2,%3}, [%4];"
                 : "=r"(r[0]), "=r"(r[1]), "=r"(r[2]), "=r"(r[3]) : "r"(a));
}
__device__ __forceinline__ void cpa16(char* dst, const void* src) {
    uint32_t s = (uint32_t)__cvta_generic_to_shared(dst);
    asm volatile("cp.async.cg.shared.global [%0], [%1], 16;" :: "r"(s), "l"(src));
}
__device__ __forceinline__ void cpa_commit() {
    asm volatile("cp.async.commit_group;" ::: "memory");
}
__device__ __forceinline__ void cpa_wait0() {
    asm volatile("cp.async.wait_group 0;" ::: "memory");
}

// ---------------- block scan (exclusive) ----------------
__device__ __forceinline__ void block_scan(int v, int& excl, int& total) {
    const int tid  = threadIdx.x;
    const int lane = tid & 31, wrp = tid >> 5;
    const int nw   = blockDim.x >> 5;
    __shared__ int wsum[32];
    int inc = v;
#pragma unroll
    for (int o = 1; o < 32; o <<= 1) {
        int n = __shfl_up_sync(0xFFFFFFFFu, inc, o);
        if (lane >= o) inc += n;
    }
    if (lane == 31) wsum[wrp] = inc;
    __syncthreads();
    if (wrp == 0) {
        int w = (lane < nw) ? wsum[lane] : 0;
#pragma unroll
        for (int o = 1; o < 32; o <<= 1) {
            int n = __shfl_up_sync(0xFFFFFFFFu, w, o);
            if (lane >= o) w += n;
        }
        wsum[lane] = w;
    }
    __syncthreads();
    int woff = wrp ? wsum[wrp - 1] : 0;
    excl  = woff + inc - v;
    total = wsum[nw - 1];
    __syncthreads();
}

// ---------------- fused: top-k + cls/mask epilogue + w2 hi/lo split ----------------
__global__ __launch_bounds__(TOPK_NT)
void topk_kernel(const float* __restrict__ expr,
                 const float* __restrict__ w2,
                 const float* __restrict__ cls,
                 float* __restrict__ out,
                 int B, int G, int K, int hasMask) {
    const int tid = threadIdx.x;

    if (blockIdx.x >= (unsigned)B) {
        // ---- w2 split path: 16 blocks x 1024 threads x 4 elems ----
        int idx = ((blockIdx.x - B) * TOPK_NT + tid) * 4;
        if (idx < D_DIM * D_DIM) {
            float4 w = *(const float4*)(&w2[idx]);
            float wv[4] = {w.x, w.y, w.z, w.w};
            uint32_t hpack[2], lpack[2];
            unsigned short hs[4], ls[4];
#pragma unroll
            for (int j = 0; j < 4; ++j) {
                __nv_bfloat16 hi = __float2bfloat16(wv[j]);
                float lo_f = wv[j] - __bfloat162float(hi);
                __nv_bfloat16 lo = __float2bfloat16(lo_f);
                hs[j] = *(unsigned short*)&hi;
                ls[j] = *(unsigned short*)&lo;
            }
            hpack[0] = hs[0] | ((uint32_t)hs[1] << 16);
            hpack[1] = hs[2] | ((uint32_t)hs[3] << 16);
            lpack[0] = ls[0] | ((uint32_t)ls[1] << 16);
            lpack[1] = ls[2] | ((uint32_t)ls[3] << 16);
            *(uint2*)(&g_w2hi[idx]) = make_uint2(hpack[0], hpack[1]);
            *(uint2*)(&g_w2lo[idx]) = make_uint2(lpack[0], lpack[1]);
        }
        return;
    }

    const int b = blockIdx.x;
    const float* __restrict__ row = expr + (size_t)b * G;

    __shared__ unsigned int hist[256];
    __shared__ unsigned int s_prefix;
    __shared__ int s_remaining;

    const int base = tid * SEG;
    unsigned keys[SEG];
    if (base + SEG <= G) {
#pragma unroll
        for (int i = 0; i < SEG; i += 4) {
            float4 v = *(const float4*)(&row[base + i]);
            keys[i + 0] = __float_as_uint(v.x);
            keys[i + 1] = __float_as_uint(v.y);
            keys[i + 2] = __float_as_uint(v.z);
            keys[i + 3] = __float_as_uint(v.w);
        }
    } else {
#pragma unroll
        for (int i = 0; i < SEG; ++i)
            keys[i] = (base + i < G) ? __float_as_uint(row[base + i]) : 0u;
    }

    if (tid == 0) { s_prefix = 0u; s_remaining = K; }
    __syncthreads();

#pragma unroll
    for (int pass = 0; pass < 4; ++pass) {
        const int shift = 24 - 8 * pass;
        const unsigned maskHigh = (pass == 0) ? 0u : (0xFFFFFFFFu << (shift + 8));
        if (tid < 256) hist[tid] = 0u;
        __syncthreads();
        const unsigned prefix = s_prefix;
        const int rem = s_remaining;
#pragma unroll
        for (int i = 0; i < SEG; ++i) {
            unsigned key = keys[i];
            if ((key & maskHigh) == prefix)
                atomicAdd(&hist[(key >> shift) & 0xFFu], 1u);
        }
        __syncthreads();
        int v = (tid < 256) ? (int)hist[255 - tid] : 0;
        int excl, total;
        block_scan(v, excl, total);
        int incl = excl + v;
        if (tid < 256 && incl >= rem && excl < rem) {
            s_prefix    = prefix | ((unsigned)(255 - tid) << shift);
            s_remaining = rem - excl;
        }
        __syncthreads();
    }
    const unsigned pivot = s_prefix;
    const int r = s_remaining;

    int n_gt = 0, n_eq = 0;
#pragma unroll
    for (int i = 0; i < SEG; ++i) {
        n_gt += (keys[i] > pivot);
        n_eq += (keys[i] == pivot);
    }
    int eq_base, eq_tot;
    block_scan(n_eq, eq_base, eq_tot);
    int eq_keep = 0;
    if (pivot > 0u) {
        int take = r - eq_base;
        eq_keep = take < 0 ? 0 : (take > n_eq ? n_eq : take);
    }
    int n_keep = n_gt + eq_keep;
    int out_base, out_tot;
    block_scan(n_keep, out_base, out_tot);

    int pos = out_base, erank = eq_base;
    int* __restrict__ sel = g_sel + b * MAXK;
#pragma unroll
    for (int i = 0; i < SEG; ++i) {
        unsigned key = keys[i];
        if (key > pivot) {
            sel[pos++] = base + i;
        } else if (key == pivot) {
            if (pivot > 0u && erank < r) sel[pos++] = base + i;
            ++erank;
        }
    }
    const int cnt = (out_tot < K) ? out_tot : K;
    if (tid == 0) g_cnt[b] = cnt;

    // ---- fused cls row + mask epilogue ----
    const size_t rowsz = (size_t)(K + 1) * D_DIM;
    float* orow = out + (size_t)b * rowsz;
    if (tid < D_DIM) orow[tid] = cls[tid];
    if (hasMask) {
        float* mask = out + (size_t)B * rowsz + (size_t)b * (K + 1);
        for (int j = tid; j < K + 1; j += TOPK_NT)
            mask[j] = (j == 0 || (j - 1) < cnt) ? 1.0f : 0.0f;
    }
}

// ---------------- token GEMM via mma.sync bf16 (3-pass hi/lo, pipelined) ----------------
// Block: 512 threads = 16 warps (2 x 8). Block tile 128 tokens x 256 outputs.
// Warp tile: 64 tokens x 32 outputs (mi=4, ni=4). K = 256 in 4 chunks of 64.
// Swizzled smem (128B rows, off ^= (row&7)<<4), cp.async.cg B fills, 2-stage pipeline.
__global__ __launch_bounds__(GEMM_NT, 1)
void gemm_kernel(const float* __restrict__ expr,
                 const float* __restrict__ gene_emb,
                 const float* __restrict__ w1,
                 const float* __restrict__ b1,
                 const float* __restrict__ b2,
                 float* __restrict__ out,
                 int B, int G, int K) {
    extern __shared__ char dyn[];

    __shared__ float sx[MT];
    __shared__ int   sgm[MT];
    __shared__ float sw1[D_DIM], sb1[D_DIM], sb2[D_DIM];

    const int tid  = threadIdx.x;
    const int wid  = tid >> 5, lane = tid & 31;
    const int wm   = wid >> 3;            // 0..1 (token dim, 64 each)
    const int wn   = wid & 7;             // 0..7 (output dim, 32 each)
    const int gr   = lane >> 2;           // 0..7
    const int cq   = lane & 3;            // 0..3
    const int t0   = blockIdx.x * MT;
    const int bb   = t0 / K;              // K % MT == 0

    if (tid < MT) {
        int k = t0 - bb * K + tid;
        int g = -1; float x = 0.0f;
        if (bb < B && k < g_cnt[bb]) {
            g = g_sel[bb * MAXK + k];
            x = expr[(size_t)bb * G + g];
        }
        sgm[tid] = g; sx[tid] = x;
    }
    if (tid < D_DIM) { sw1[tid] = w1[tid]; sb1[tid] = b1[tid]; sb2[tid] = b2[tid]; }
    __syncthreads();

    float acc[4][4][4];
#pragma unroll
    for (int mi = 0; mi < 4; ++mi)
#pragma unroll
        for (int ni = 0; ni < 4; ++ni)
#pragma unroll
            for (int j = 0; j < 4; ++j) acc[mi][ni][j] = 0.0f;

    // per-thread fill constants (512 threads)
    const int at  = tid >> 2;             // token row 0..127 for A fill
    const int kh  = (tid & 3) * 16;       // k offset base for A fill (16 elems/thread)
    const float ax = sx[at];
    const uint32_t a_fill_base = (uint32_t)(at * 128);
    const uint32_t a_fill_x    = (uint32_t)((at & 7) << 4);
    const int bn0 = tid >> 3;             // 0..63 B fill row base
    const int bk16 = tid & 7;             // 16B group

    // per-thread ldmatrix constants
    const int a_r   = (lane & 7) + ((lane >> 3) & 1) * 8;   // row-in-16 for A tiles
    const uint32_t a_kb4 = (uint32_t)((lane >> 4) << 4);    // k 16B-group bit
    const int b_r   = (lane & 7) + ((lane >> 4) & 1) * 8;
    const uint32_t b_kb4 = (uint32_t)(((lane >> 3) & 1) << 4);
    const uint32_t xo = (uint32_t)((lane & 7) << 4);        // swizzle xor (row&7)<<4

    // ---- fill helpers as lambdas ----
    auto fillB = [&](int c, int buf) {
        char* Bh = dyn + OFF_B + buf * B_BUF;
        char* Bl = Bh + B_HALF;
        const int d0 = c * KC;
#pragma unroll
        for (int i = 0; i < 4; ++i) {
            int n = bn0 + 64 * i;
            uint32_t doff = (uint32_t)(n * 128) + (((uint32_t)(bk16 * 16)) ^ ((uint32_t)((n & 7) << 4)));
            const __nv_bfloat16* sh = &g_w2hi[(size_t)n * D_DIM + d0 + bk16 * 8];
            const __nv_bfloat16* sl = &g_w2lo[(size_t)n * D_DIM + d0 + bk16 * 8];
            cpa16(Bh + doff, sh);
            cpa16(Bl + doff, sl);
        }
        cpa_commit();
    };
    auto fillA = [&](int c, int buf) {
        char* Ah = dyn + buf * A_BUF;
        char* Al = Ah + A_HALF;
        const int d0 = c * KC;
#pragma unroll
        for (int j = 0; j < 8; ++j) {
            int kk = kh + 2 * j;
            int d  = d0 + kk;
            float z0 = fmaf(ax, sw1[d], sb1[d]);
            float z1 = fmaf(ax, sw1[d + 1], sb1[d + 1]);
            float h0 = 0.5f * z0 * (1.0f + erff(z0 * 0.70710678118654752f));
            float h1 = 0.5f * z1 * (1.0f + erff(z1 * 0.70710678118654752f));
            __nv_bfloat16 hi0 = __float2bfloat16(h0);
            __nv_bfloat16 hi1 = __float2bfloat16(h1);
            __nv_bfloat16 lo0 = __float2bfloat16(h0 - __bfloat162float(hi0));
            __nv_bfloat16 lo1 = __float2bfloat16(h1 - __bfloat162float(hi1));
            uint32_t hp = (uint32_t)*(unsigned short*)&hi0 | ((uint32_t)*(unsigned short*)&hi1 << 16);
            uint32_t lp = (uint32_t)*(unsigned short*)&lo0 | ((uint32_t)*(unsigned short*)&lo1 << 16);
            uint32_t boff = a_fill_base + (((uint32_t)(2 * kk)) ^ a_fill_x);
            *(uint32_t*)(Ah + boff) = hp;
            *(uint32_t*)(Al + boff) = lp;
        }
    };

    // ---- prologue: stage chunk 0 ----
    fillB(0, 0);
    fillA(0, 0);
    cpa_wait0();
    __syncthreads();

    for (int c = 0; c < NCHUNK; ++c) {
        const int cur = c & 1, nxt = cur ^ 1;
        if (c < NCHUNK - 1) { fillB(c + 1, nxt); fillA(c + 1, nxt); }

        char* Ah = dyn + cur * A_BUF;
        char* Al = Ah + A_HALF;
        char* Bh = dyn + OFF_B + cur * B_BUF;
        char* Bl = Bh + B_HALF;

#pragma unroll
        for (int ks = 0; ks < 4; ++ks) {
            const uint32_t kb2 = (uint32_t)(ks * 32);
            const uint32_t aks = (kb2 | a_kb4) ^ xo;
            const uint32_t bks = (kb2 | b_kb4) ^ xo;
            uint32_t ahi[4][4], alo[4][4];
#pragma unroll
            for (int mi = 0; mi < 4; ++mi) {
                const uint32_t aoff = (uint32_t)((wm * 64 + mi * 16 + a_r) * 128) + aks;
                ldm_x4(ahi[mi], Ah + aoff);
                ldm_x4(alo[mi], Al + aoff);
            }
#pragma unroll
            for (int p = 0; p < 2; ++p) {
                const uint32_t boff = (uint32_t)((wn * 32 + p * 16 + b_r) * 128) + bks;
                uint32_t bh[4], bl[4];
                ldm_x4(bh, Bh + boff);
                ldm_x4(bl, Bl + boff);
#pragma unroll
                for (int half = 0; half < 2; ++half) {
                    const int ni = p * 2 + half;
                    const uint32_t* bhv = bh + half * 2;
                    const uint32_t* blv = bl + half * 2;
                    // pass-outer ordering: same-acc MMAs are 4 apart (better ILP)
#pragma unroll
                    for (int mi = 0; mi < 4; ++mi) mma_bf16(acc[mi][ni], ahi[mi], bhv);
#pragma unroll
                    for (int mi = 0; mi < 4; ++mi) mma_bf16(acc[mi][ni], ahi[mi], blv);
#pragma unroll
                    for (int mi = 0; mi < 4; ++mi) mma_bf16(acc[mi][ni], alo[mi], bhv);
                }
            }
        }
        if (c < NCHUNK - 1) cpa_wait0();
        __syncthreads();
    }

    // ---------------- epilogue ----------------
#pragma unroll
    for (int mi = 0; mi < 4; ++mi) {
#pragma unroll
        for (int half = 0; half < 2; ++half) {
            int t_local = wm * 64 + mi * 16 + gr + half * 8;
            int g = sgm[t_local];
            int k_in = t0 + t_local - bb * K;
            size_t rowoff = ((size_t)bb * (K + 1) + (k_in + 1)) * D_DIM;
#pragma unroll
            for (int ni = 0; ni < 4; ++ni) {
                int e = wn * 32 + ni * 8 + 2 * cq;
                float c0 = acc[mi][ni][half * 2 + 0];
                float c1 = acc[mi][ni][half * 2 + 1];
                float2 v;
                if (g >= 0) {
                    float2 ge = *(const float2*)(&gene_emb[(size_t)g * D_DIM + e]);
                    v.x = c0 + ge.x + sb2[e + 0];
                    v.y = c1 + ge.y + sb2[e + 1];
                } else {
                    v = make_float2(0.f, 0.f);
                }
                *(float2*)(&out[rowoff + e]) = v;
            }
        }
    }
}

extern "C" void kernel_launch(void* const* d_in, const int* in_sizes, int n_in,
                              void* d_out, int out_size) {
    const float* expr     = (const float*)d_in[0];
    const float* gene_emb = (const float*)d_in[1];
    const float* w1       = (const float*)d_in[2];
    const float* b1       = (const float*)d_in[3];
    const float* w2       = (const float*)d_in[4];
    const float* b2       = (const float*)d_in[5];
    const float* cls      = (const float*)d_in[6];
    float* out = (float*)d_out;

    const int D = in_sizes[2];              // 256
    const int G = in_sizes[1] / D;          // 20000
    const int B = in_sizes[0] / G;          // 16

    long Kp1; int hasMask;
    if (out_size % ((long)B * (D + 1)) == 0) {
        Kp1 = out_size / ((long)B * (D + 1));
        hasMask = 1;
    } else {
        Kp1 = out_size / ((long)B * D);
        hasMask = 0;
    }
    const int K = (int)Kp1 - 1;             // 2048
    if (B > MAXB || K > MAXK || D != D_DIM) return;
    if (TOPK_NT * SEG < G) return;
    if (K % MT != 0) return;

    cudaFuncSetAttribute(gemm_kernel,
                         cudaFuncAttributeMaxDynamicSharedMemorySize, DYN_BYTES);

    topk_kernel<<<B + WSPLIT_BLOCKS, TOPK_NT>>>(expr, w2, cls, out, B, G, K, hasMask);

    int tiles = (B * K) / MT;               // 256
    gemm_kernel<<<tiles, GEMM_NT, DYN_BYTES>>>(expr, gene_emb, w1, b1, b2, out, B, G, K);
}

// round 12
// speedup vs baseline: 2.2948x; 2.1039x over previous
#include <cuda_runtime.h>
#include <cuda_bf16.h>
#include <math.h>
#include <stdint.h>

#define D_DIM 256
#define MAXB  64
#define MAXK  4096
#define TOPK_NT 1024
#define SEG   20

#define TBL     4096              // interpolation table size
#define TGM_MT  32                // grid rows per table-GEMM block
#define TGM_BLOCKS (TBL / TGM_MT) // 128
#define KC      64                // K elements per chunk
#define NCHUNK  (D_DIM / KC)      // 4
// dynamic smem (table-GEMM path): A hi/lo then B hi/lo, 128B rows, XOR swizzle
#define A_HALF  (TGM_MT * 128)    // 4096 B
#define OFF_B   (2 * A_HALF)      // 8192
#define B_HALF  (D_DIM * 128)     // 32768 B
#define DYN_BYTES (2 * A_HALF + 2 * B_HALF)   // 73728

// scratch (no cudaMalloc allowed)
__device__ int g_sel[MAXB * MAXK];
__device__ int g_cnt[MAXB];
__device__ float g_tbl[TBL * D_DIM];          // F(x_i) + b2, 4 MB

// ---------------- mma / ldmatrix helpers ----------------
__device__ __forceinline__ void mma_bf16(float* c, const uint32_t* a, const uint32_t* b) {
    asm volatile(
        "mma.sync.aligned.m16n8k16.row.col.f32.bf16.bf16.f32 "
        "{%0,%1,%2,%3}, {%4,%5,%6,%7}, {%8,%9}, {%0,%1,%2,%3};"
        : "+f"(c[0]), "+f"(c[1]), "+f"(c[2]), "+f"(c[3])
        : "r"(a[0]), "r"(a[1]), "r"(a[2]), "r"(a[3]), "r"(b[0]), "r"(b[1]));
}
__device__ __forceinline__ void ldm_x4(uint32_t* r, const char* p) {
    uint32_t a = (uint32_t)__cvta_generic_to_shared(p);
    asm volatile("ldmatrix.sync.aligned.m8n8.x4.shared.b16 {%0,%1,%2,%3}, [%4];"
                 : "=r"(r[0]), "=r"(r[1]), "=r"(r[2]), "=r"(r[3]) : "r"(a));
}

// ---------------- block scan (exclusive) ----------------
__device__ __forceinline__ void block_scan(int v, int& excl, int& total) {
    const int tid  = threadIdx.x;
    const int lane = tid & 31, wrp = tid >> 5;
    const int nw   = blockDim.x >> 5;
    __shared__ int wsum[32];
    int inc = v;
#pragma unroll
    for (int o = 1; o < 32; o <<= 1) {
        int n = __shfl_up_sync(0xFFFFFFFFu, inc, o);
        if (lane >= o) inc += n;
    }
    if (lane == 31) wsum[wrp] = inc;
    __syncthreads();
    if (wrp == 0) {
        int w = (lane < nw) ? wsum[lane] : 0;
#pragma unroll
        for (int o = 1; o < 32; o <<= 1) {
            int n = __shfl_up_sync(0xFFFFFFFFu, w, o);
            if (lane >= o) w += n;
        }
        wsum[lane] = w;
    }
    __syncthreads();
    int woff = wrp ? wsum[wrp - 1] : 0;
    excl  = woff + inc - v;
    total = wsum[nw - 1];
    __syncthreads();
}

__device__ __forceinline__ float gelu_exact(float z) {
    return 0.5f * z * (1.0f + erff(z * 0.70710678118654752f));
}
__device__ __forceinline__ void split_bf16(float v, unsigned short& h, unsigned short& l) {
    __nv_bfloat16 hb = __float2bfloat16(v);
    __nv_bfloat16 lb = __float2bfloat16(v - __bfloat162float(hb));
    h = *(unsigned short*)&hb;
    l = *(unsigned short*)&lb;
}

// ================= fused kernel: topk (blocks 0..B-1) + table GEMM (blocks B..B+127) =================
__global__ __launch_bounds__(TOPK_NT)
void fused_kernel(const float* __restrict__ expr,
                  const float* __restrict__ w1,
                  const float* __restrict__ b1,
                  const float* __restrict__ w2,
                  const float* __restrict__ b2,
                  const float* __restrict__ cls,
                  float* __restrict__ out,
                  int B, int G, int K, int hasMask) {
    const int tid = threadIdx.x;

    if (blockIdx.x >= (unsigned)B) {
        // ================== table GEMM path ==================
        // Block tile: 32 grid-rows x 256 outputs. 32 warps: wm 0..1 (16 rows), wn 0..15 (16 cols).
        extern __shared__ char dyn[];
        __shared__ float sw1[D_DIM], sb1[D_DIM], sb2g[D_DIM];

        const int bid  = blockIdx.x - B;
        const int wid  = tid >> 5, lane = tid & 31;
        const int wm   = wid >> 4;            // 0..1
        const int wn   = wid & 15;            // 0..15
        const int gr   = lane >> 2;           // 0..7
        const int cq   = lane & 3;            // 0..3

        if (tid < D_DIM) { sw1[tid] = w1[tid]; sb1[tid] = b1[tid]; sb2g[tid] = b2[tid]; }
        __syncthreads();

        float acc[2][4];
#pragma unroll
        for (int ni = 0; ni < 2; ++ni)
#pragma unroll
            for (int j = 0; j < 4; ++j) acc[ni][j] = 0.0f;

        // fill constants
        const int at  = tid >> 5;             // 0..31 grid row (A fill)
        const int k2  = (lane) * 2;           // 2 k-elems per thread per chunk
        const float xg = (float)(bid * TGM_MT + at) * (1.0f / (float)(TBL - 1));
        const int bn  = tid >> 2;             // 0..255 output row (B fill)
        const int bkq = (tid & 3) * 16;       // 16 k-elems per thread per chunk

        // ldmatrix constants
        const int a_r   = (lane & 7) + ((lane >> 3) & 1) * 8;
        const uint32_t a_kb4 = (uint32_t)((lane >> 4) << 4);
        const int b_r   = (lane & 7) + ((lane >> 4) & 1) * 8;
        const uint32_t b_kb4 = (uint32_t)(((lane >> 3) & 1) << 4);
        const uint32_t xo = (uint32_t)((lane & 7) << 4);

        char* const Ah = dyn;
        char* const Al = dyn + A_HALF;
        char* const Bh = dyn + OFF_B;
        char* const Bl = dyn + OFF_B + B_HALF;

        for (int c = 0; c < NCHUNK; ++c) {
            const int d0 = c * KC;
            // --- A fill: h = gelu(xg*w1+b1), hi/lo, 2 elems/thread ---
            {
                int d = d0 + k2;
                float h0 = gelu_exact(fmaf(xg, sw1[d],     sb1[d]));
                float h1 = gelu_exact(fmaf(xg, sw1[d + 1], sb1[d + 1]));
                unsigned short h0h, h0l, h1h, h1l;
                split_bf16(h0, h0h, h0l);
                split_bf16(h1, h1h, h1l);
                uint32_t hp = (uint32_t)h0h | ((uint32_t)h1h << 16);
                uint32_t lp = (uint32_t)h0l | ((uint32_t)h1l << 16);
                uint32_t boff = (uint32_t)(at * 128) + (((uint32_t)(k2 * 2)) ^ ((uint32_t)((at & 7) << 4)));
                *(uint32_t*)(Ah + boff) = hp;
                *(uint32_t*)(Al + boff) = lp;
            }
            // --- B fill: w2 fp32 -> split hi/lo, 16 elems/thread ---
            {
                const float* src = &w2[(size_t)bn * D_DIM + d0 + bkq];
                uint32_t rowbase = (uint32_t)(bn * 128);
                uint32_t xorn = (uint32_t)((bn & 7) << 4);
#pragma unroll
                for (int grp = 0; grp < 2; ++grp) {
                    float4 v0 = *(const float4*)(src + grp * 8);
                    float4 v1 = *(const float4*)(src + grp * 8 + 4);
                    float vv[8] = {v0.x, v0.y, v0.z, v0.w, v1.x, v1.y, v1.z, v1.w};
                    unsigned short hs[8], ls[8];
#pragma unroll
                    for (int j = 0; j < 8; ++j) split_bf16(vv[j], hs[j], ls[j]);
                    uint4 hq, lq;
                    hq.x = (uint32_t)hs[0] | ((uint32_t)hs[1] << 16);
                    hq.y = (uint32_t)hs[2] | ((uint32_t)hs[3] << 16);
                    hq.z = (uint32_t)hs[4] | ((uint32_t)hs[5] << 16);
                    hq.w = (uint32_t)hs[6] | ((uint32_t)hs[7] << 16);
                    lq.x = (uint32_t)ls[0] | ((uint32_t)ls[1] << 16);
                    lq.y = (uint32_t)ls[2] | ((uint32_t)ls[3] << 16);
                    lq.z = (uint32_t)ls[4] | ((uint32_t)ls[5] << 16);
                    lq.w = (uint32_t)ls[6] | ((uint32_t)ls[7] << 16);
                    uint32_t boff = rowbase + (((uint32_t)(bkq * 2 + grp * 16)) ^ xorn);
                    *(uint4*)(Bh + boff) = hq;
                    *(uint4*)(Bl + boff) = lq;
                }
            }
            __syncthreads();

            // --- mainloop: 4 k-steps of 16 ---
#pragma unroll
            for (int ks = 0; ks < 4; ++ks) {
                const uint32_t kb2 = (uint32_t)(ks * 32);
                const uint32_t aks = (kb2 | a_kb4) ^ xo;
                const uint32_t bks = (kb2 | b_kb4) ^ xo;
                uint32_t ahi[4], alo[4], bh[4], bl[4];
                const uint32_t aoff = (uint32_t)((wm * 16 + a_r) * 128) + aks;
                ldm_x4(ahi, Ah + aoff);
                ldm_x4(alo, Al + aoff);
                const uint32_t boff = (uint32_t)((wn * 16 + b_r) * 128) + bks;
                ldm_x4(bh, Bh + boff);
                ldm_x4(bl, Bl + boff);
#pragma unroll
                for (int half = 0; half < 2; ++half) {
                    const uint32_t* bhv = bh + half * 2;
                    const uint32_t* blv = bl + half * 2;
                    mma_bf16(acc[half], ahi, bhv);
                    mma_bf16(acc[half], ahi, blv);
                    mma_bf16(acc[half], alo, bhv);
                }
            }
            __syncthreads();
        }

        // epilogue: table row = F(xg) + b2
#pragma unroll
        for (int h8 = 0; h8 < 2; ++h8) {
            int row = bid * TGM_MT + wm * 16 + gr + h8 * 8;
#pragma unroll
            for (int ni = 0; ni < 2; ++ni) {
                int e = wn * 16 + ni * 8 + 2 * cq;
                float2 v;
                v.x = acc[ni][h8 * 2 + 0] + sb2g[e];
                v.y = acc[ni][h8 * 2 + 1] + sb2g[e + 1];
                *(float2*)(&g_tbl[(size_t)row * D_DIM + e]) = v;
            }
        }
        return;
    }

    // ================== top-k path ==================
    const int b = blockIdx.x;
    const float* __restrict__ row = expr + (size_t)b * G;

    __shared__ unsigned int hist[256];
    __shared__ unsigned int s_prefix;
    __shared__ int s_remaining;

    const int base = tid * SEG;
    unsigned keys[SEG];
    if (base + SEG <= G) {
#pragma unroll
        for (int i = 0; i < SEG; i += 4) {
            float4 v = *(const float4*)(&row[base + i]);
            keys[i + 0] = __float_as_uint(v.x);
            keys[i + 1] = __float_as_uint(v.y);
            keys[i + 2] = __float_as_uint(v.z);
            keys[i + 3] = __float_as_uint(v.w);
        }
    } else {
#pragma unroll
        for (int i = 0; i < SEG; ++i)
            keys[i] = (base + i < G) ? __float_as_uint(row[base + i]) : 0u;
    }

    if (tid == 0) { s_prefix = 0u; s_remaining = K; }
    __syncthreads();

#pragma unroll
    for (int pass = 0; pass < 4; ++pass) {
        const int shift = 24 - 8 * pass;
        const unsigned maskHigh = (pass == 0) ? 0u : (0xFFFFFFFFu << (shift + 8));
        if (tid < 256) hist[tid] = 0u;
        __syncthreads();
        const unsigned prefix = s_prefix;
        const int rem = s_remaining;
#pragma unroll
        for (int i = 0; i < SEG; ++i) {
            unsigned key = keys[i];
            if ((key & maskHigh) == prefix)
                atomicAdd(&hist[(key >> shift) & 0xFFu], 1u);
        }
        __syncthreads();
        int v = (tid < 256) ? (int)hist[255 - tid] : 0;
        int excl, total;
        block_scan(v, excl, total);
        int incl = excl + v;
        if (tid < 256 && incl >= rem && excl < rem) {
            s_prefix    = prefix | ((unsigned)(255 - tid) << shift);
            s_remaining = rem - excl;
        }
        __syncthreads();
    }
    const unsigned pivot = s_prefix;
    const int r = s_remaining;

    int n_gt = 0, n_eq = 0;
#pragma unroll
    for (int i = 0; i < SEG; ++i) {
        n_gt += (keys[i] > pivot);
        n_eq += (keys[i] == pivot);
    }
    int eq_base, eq_tot;
    block_scan(n_eq, eq_base, eq_tot);
    int eq_keep = 0;
    if (pivot > 0u) {
        int take = r - eq_base;
        eq_keep = take < 0 ? 0 : (take > n_eq ? n_eq : take);
    }
    int n_keep = n_gt + eq_keep;
    int out_base, out_tot;
    block_scan(n_keep, out_base, out_tot);

    int pos = out_base, erank = eq_base;
    int* __restrict__ sel = g_sel + b * MAXK;
#pragma unroll
    for (int i = 0; i < SEG; ++i) {
        unsigned key = keys[i];
        if (key > pivot) {
            sel[pos++] = base + i;
        } else if (key == pivot) {
            if (pivot > 0u && erank < r) sel[pos++] = base + i;
            ++erank;
        }
    }
    const int cnt = (out_tot < K) ? out_tot : K;
    if (tid == 0) g_cnt[b] = cnt;

    // ---- fused cls row + mask epilogue ----
    const size_t rowsz = (size_t)(K + 1) * D_DIM;
    float* orow = out + (size_t)b * rowsz;
    if (tid < D_DIM) orow[tid] = cls[tid];
    if (hasMask) {
        float* mask = out + (size_t)B * rowsz + (size_t)b * (K + 1);
        for (int j = tid; j < K + 1; j += TOPK_NT)
            mask[j] = (j == 0 || (j - 1) < cnt) ? 1.0f : 0.0f;
    }
}

// ================= interp/gather kernel =================
// 512 threads: 8 tokens per block, 64 threads per token (4 floats each).
__global__ __launch_bounds__(512)
void interp_kernel(const float* __restrict__ expr,
                   const float* __restrict__ gene_emb,
                   float* __restrict__ out,
                   int B, int G, int K) {
    __shared__ int   sg[8];
    __shared__ int   si0[8];
    __shared__ float sf[8];

    const int tid = threadIdx.x;
    if (tid < 8) {
        int tkn = blockIdx.x * 8 + tid;
        int b = tkn / K, k = tkn - b * K;
        int g = -1, i0 = 0; float f = 0.0f;
        if (k < g_cnt[b]) {
            g = g_sel[b * MAXK + k];
            float x = expr[(size_t)b * G + g];
            float u = x * (float)(TBL - 1);
            i0 = (int)u;
            if (i0 < 0) i0 = 0;
            if (i0 > TBL - 2) i0 = TBL - 2;
            f = u - (float)i0;
        }
        sg[tid] = g; si0[tid] = i0; sf[tid] = f;
    }
    __syncthreads();

    const int j   = tid >> 6;              // token within block
    const int e4  = (tid & 63) << 2;       // element offset
    const int tkn = blockIdx.x * 8 + j;
    const int b = tkn / K, k = tkn - b * K;
    const int g = sg[j];

    float4 v;
    if (g >= 0) {
        const int i0 = si0[j];
        const float f = sf[j];
        float4 t0 = *(const float4*)(&g_tbl[(size_t)i0 * D_DIM + e4]);
        float4 t1 = *(const float4*)(&g_tbl[(size_t)(i0 + 1) * D_DIM + e4]);
        float4 ge = *(const float4*)(&gene_emb[(size_t)g * D_DIM + e4]);
        v.x = fmaf(t1.x - t0.x, f, t0.x) + ge.x;
        v.y = fmaf(t1.y - t0.y, f, t0.y) + ge.y;
        v.z = fmaf(t1.z - t0.z, f, t0.z) + ge.z;
        v.w = fmaf(t1.w - t0.w, f, t0.w) + ge.w;
    } else {
        v = make_float4(0.f, 0.f, 0.f, 0.f);
    }
    size_t rowoff = ((size_t)b * (K + 1) + (k + 1)) * D_DIM;
    *(float4*)(&out[rowoff + e4]) = v;
}

extern "C" void kernel_launch(void* const* d_in, const int* in_sizes, int n_in,
                              void* d_out, int out_size) {
    const float* expr     = (const float*)d_in[0];
    const float* gene_emb = (const float*)d_in[1];
    const float* w1       = (const float*)d_in[2];
    const float* b1       = (const float*)d_in[3];
    const float* w2       = (const float*)d_in[4];
    const float* b2       = (const float*)d_in[5];
    const float* cls      = (const float*)d_in[6];
    float* out = (float*)d_out;

    const int D = in_sizes[2];              // 256
    const int G = in_sizes[1] / D;          // 20000
    const int B = in_sizes[0] / G;          // 16

    long Kp1; int hasMask;
    if (out_size % ((long)B * (D + 1)) == 0) {
        Kp1 = out_size / ((long)B * (D + 1));
        hasMask = 1;
    } else {
        Kp1 = out_size / ((long)B * D);
        hasMask = 0;
    }
    const int K = (int)Kp1 - 1;             // 2048
    if (B > MAXB || K > MAXK || D != D_DIM) return;
    if (TOPK_NT * SEG < G) return;
    if ((B * K) % 8 != 0) return;

    cudaFuncSetAttribute(fused_kernel,
                         cudaFuncAttributeMaxDynamicSharedMemorySize, DYN_BYTES);

    fused_kernel<<<B + TGM_BLOCKS, TOPK_NT, DYN_BYTES>>>(
        expr, w1, b1, w2, b2, cls, out, B, G, K, hasMask);

    interp_kernel<<<(B * K) / 8, 512>>>(expr, gene_emb, out, B, G, K);
}

// round 13
// speedup vs baseline: 2.7103x; 1.1811x over previous
#include <cuda_runtime.h>
#include <cuda_bf16.h>
#include <math.h>
#include <stdint.h>

#define D_DIM 256
#define MAXB  64
#define MAXK  4096
#define TOPK_NT 1024
#define SEG   20

#define TBL     4096              // interpolation table size
#define TGM_MT  32                // grid rows per table-GEMM block
#define TGM_BLOCKS (TBL / TGM_MT) // 128
#define KC      64                // K elements per chunk
#define NCHUNK  (D_DIM / KC)      // 4
// dynamic smem (table-GEMM path): A hi/lo then B hi/lo, 128B rows, XOR swizzle
#define A_HALF  (TGM_MT * 128)    // 4096 B
#define OFF_B   (2 * A_HALF)      // 8192
#define B_HALF  (D_DIM * 128)     // 32768 B
#define DYN_BYTES (2 * A_HALF + 2 * B_HALF)   // 73728

// scratch (no cudaMalloc allowed)
__device__ int2  g_selv[MAXB * MAXK];         // {gene_idx, expr_bits}
__device__ int   g_cnt[MAXB];
__device__ float g_tbl[TBL * D_DIM];          // F(x_i) + b2, 4 MB

// ---------------- mma / ldmatrix helpers ----------------
__device__ __forceinline__ void mma_bf16(float* c, const uint32_t* a, const uint32_t* b) {
    asm volatile(
        "mma.sync.aligned.m16n8k16.row.col.f32.bf16.bf16.f32 "
        "{%0,%1,%2,%3}, {%4,%5,%6,%7}, {%8,%9}, {%0,%1,%2,%3};"
        : "+f"(c[0]), "+f"(c[1]), "+f"(c[2]), "+f"(c[3])
        : "r"(a[0]), "r"(a[1]), "r"(a[2]), "r"(a[3]), "r"(b[0]), "r"(b[1]));
}
__device__ __forceinline__ void ldm_x4(uint32_t* r, const char* p) {
    uint32_t a = (uint32_t)__cvta_generic_to_shared(p);
    asm volatile("ldmatrix.sync.aligned.m8n8.x4.shared.b16 {%0,%1,%2,%3}, [%4];"
                 : "=r"(r[0]), "=r"(r[1]), "=r"(r[2]), "=r"(r[3]) : "r"(a));
}

// ---------------- block scan (exclusive) ----------------
__device__ __forceinline__ void block_scan(int v, int& excl, int& total) {
    const int tid  = threadIdx.x;
    const int lane = tid & 31, wrp = tid >> 5;
    const int nw   = blockDim.x >> 5;
    __shared__ int wsum[32];
    int inc = v;
#pragma unroll
    for (int o = 1; o < 32; o <<= 1) {
        int n = __shfl_up_sync(0xFFFFFFFFu, inc, o);
        if (lane >= o) inc += n;
    }
    if (lane == 31) wsum[wrp] = inc;
    __syncthreads();
    if (wrp == 0) {
        int w = (lane < nw) ? wsum[lane] : 0;
#pragma unroll
        for (int o = 1; o < 32; o <<= 1) {
            int n = __shfl_up_sync(0xFFFFFFFFu, w, o);
            if (lane >= o) w += n;
        }
        wsum[lane] = w;
    }
    __syncthreads();
    int woff = wrp ? wsum[wrp - 1] : 0;
    excl  = woff + inc - v;
    total = wsum[nw - 1];
    __syncthreads();
}

__device__ __forceinline__ float gelu_exact(float z) {
    return 0.5f * z * (1.0f + erff(z * 0.70710678118654752f));
}
__device__ __forceinline__ void split_bf16(float v, unsigned short& h, unsigned short& l) {
    __nv_bfloat16 hb = __float2bfloat16(v);
    __nv_bfloat16 lb = __float2bfloat16(v - __bfloat162float(hb));
    h = *(unsigned short*)&hb;
    l = *(unsigned short*)&lb;
}

// ================= fused kernel: topk (blocks 0..B-1) + table GEMM (blocks B..B+127) =================
__global__ __launch_bounds__(TOPK_NT)
void fused_kernel(const float* __restrict__ expr,
                  const float* __restrict__ w1,
                  const float* __restrict__ b1,
                  const float* __restrict__ w2,
                  const float* __restrict__ b2,
                  const float* __restrict__ cls,
                  float* __restrict__ out,
                  int B, int G, int K, int hasMask) {
    const int tid = threadIdx.x;

    if (blockIdx.x >= (unsigned)B) {
        // ================== table GEMM path ==================
        extern __shared__ char dyn[];
        __shared__ float sw1[D_DIM], sb1[D_DIM], sb2g[D_DIM];

        const int bid  = blockIdx.x - B;
        const int wid  = tid >> 5, lane = tid & 31;
        const int wm   = wid >> 4;            // 0..1
        const int wn   = wid & 15;            // 0..15
        const int gr   = lane >> 2;           // 0..7
        const int cq   = lane & 3;            // 0..3

        if (tid < D_DIM) { sw1[tid] = w1[tid]; sb1[tid] = b1[tid]; sb2g[tid] = b2[tid]; }
        __syncthreads();

        float acc[2][4];
#pragma unroll
        for (int ni = 0; ni < 2; ++ni)
#pragma unroll
            for (int j = 0; j < 4; ++j) acc[ni][j] = 0.0f;

        // fill constants
        const int at  = tid >> 5;             // 0..31 grid row (A fill)
        const int k2  = (lane) * 2;           // 2 k-elems per thread per chunk
        const float xg = (float)(bid * TGM_MT + at) * (1.0f / (float)(TBL - 1));
        const int bn  = tid >> 2;             // 0..255 output row (B fill)
        const int bkq = (tid & 3) * 16;       // 16 k-elems per thread per chunk

        // ldmatrix constants
        const int a_r   = (lane & 7) + ((lane >> 3) & 1) * 8;
        const uint32_t a_kb4 = (uint32_t)((lane >> 4) << 4);
        const int b_r   = (lane & 7) + ((lane >> 4) & 1) * 8;
        const uint32_t b_kb4 = (uint32_t)(((lane >> 3) & 1) << 4);
        const uint32_t xo = (uint32_t)((lane & 7) << 4);

        char* const Ah = dyn;
        char* const Al = dyn + A_HALF;
        char* const Bh = dyn + OFF_B;
        char* const Bl = dyn + OFF_B + B_HALF;

        for (int c = 0; c < NCHUNK; ++c) {
            const int d0 = c * KC;
            // --- A fill: h = gelu(xg*w1+b1), hi/lo, 2 elems/thread ---
            {
                int d = d0 + k2;
                float h0 = gelu_exact(fmaf(xg, sw1[d],     sb1[d]));
                float h1 = gelu_exact(fmaf(xg, sw1[d + 1], sb1[d + 1]));
                unsigned short h0h, h0l, h1h, h1l;
                split_bf16(h0, h0h, h0l);
                split_bf16(h1, h1h, h1l);
                uint32_t hp = (uint32_t)h0h | ((uint32_t)h1h << 16);
                uint32_t lp = (uint32_t)h0l | ((uint32_t)h1l << 16);
                uint32_t boff = (uint32_t)(at * 128) + (((uint32_t)(k2 * 2)) ^ ((uint32_t)((at & 7) << 4)));
                *(uint32_t*)(Ah + boff) = hp;
                *(uint32_t*)(Al + boff) = lp;
            }
            // --- B fill: w2 fp32 -> split hi/lo, 16 elems/thread ---
            {
                const float* src = &w2[(size_t)bn * D_DIM + d0 + bkq];
                uint32_t rowbase = (uint32_t)(bn * 128);
                uint32_t xorn = (uint32_t)((bn & 7) << 4);
#pragma unroll
                for (int grp = 0; grp < 2; ++grp) {
                    float4 v0 = *(const float4*)(src + grp * 8);
                    float4 v1 = *(const float4*)(src + grp * 8 + 4);
                    float vv[8] = {v0.x, v0.y, v0.z, v0.w, v1.x, v1.y, v1.z, v1.w};
                    unsigned short hs[8], ls[8];
#pragma unroll
                    for (int j = 0; j < 8; ++j) split_bf16(vv[j], hs[j], ls[j]);
                    uint4 hq, lq;
                    hq.x = (uint32_t)hs[0] | ((uint32_t)hs[1] << 16);
                    hq.y = (uint32_t)hs[2] | ((uint32_t)hs[3] << 16);
                    hq.z = (uint32_t)hs[4] | ((uint32_t)hs[5] << 16);
                    hq.w = (uint32_t)hs[6] | ((uint32_t)hs[7] << 16);
                    lq.x = (uint32_t)ls[0] | ((uint32_t)ls[1] << 16);
                    lq.y = (uint32_t)ls[2] | ((uint32_t)ls[3] << 16);
                    lq.z = (uint32_t)ls[4] | ((uint32_t)ls[5] << 16);
                    lq.w = (uint32_t)ls[6] | ((uint32_t)ls[7] << 16);
                    uint32_t boff = rowbase + (((uint32_t)(bkq * 2 + grp * 16)) ^ xorn);
                    *(uint4*)(Bh + boff) = hq;
                    *(uint4*)(Bl + boff) = lq;
                }
            }
            __syncthreads();

            // --- mainloop: 4 k-steps of 16 ---
#pragma unroll
            for (int ks = 0; ks < 4; ++ks) {
                const uint32_t kb2 = (uint32_t)(ks * 32);
                const uint32_t aks = (kb2 | a_kb4) ^ xo;
                const uint32_t bks = (kb2 | b_kb4) ^ xo;
                uint32_t ahi[4], alo[4], bh[4], bl[4];
                const uint32_t aoff = (uint32_t)((wm * 16 + a_r) * 128) + aks;
                ldm_x4(ahi, Ah + aoff);
                ldm_x4(alo, Al + aoff);
                const uint32_t boff = (uint32_t)((wn * 16 + b_r) * 128) + bks;
                ldm_x4(bh, Bh + boff);
                ldm_x4(bl, Bl + boff);
#pragma unroll
                for (int half = 0; half < 2; ++half) {
                    const uint32_t* bhv = bh + half * 2;
                    const uint32_t* blv = bl + half * 2;
                    mma_bf16(acc[half], ahi, bhv);
                    mma_bf16(acc[half], ahi, blv);
                    mma_bf16(acc[half], alo, bhv);
                }
            }
            __syncthreads();
        }

        // epilogue: table row = F(xg) + b2
#pragma unroll
        for (int h8 = 0; h8 < 2; ++h8) {
            int row = bid * TGM_MT + wm * 16 + gr + h8 * 8;
#pragma unroll
            for (int ni = 0; ni < 2; ++ni) {
                int e = wn * 16 + ni * 8 + 2 * cq;
                float2 v;
                v.x = acc[ni][h8 * 2 + 0] + sb2g[e];
                v.y = acc[ni][h8 * 2 + 1] + sb2g[e + 1];
                *(float2*)(&g_tbl[(size_t)row * D_DIM + e]) = v;
            }
        }
        return;
    }

    // ================== top-k path ==================
    const int b = blockIdx.x;
    const float* __restrict__ row = expr + (size_t)b * G;

    __shared__ unsigned int hist[256];
    __shared__ unsigned int s_prefix;
    __shared__ int s_remaining;

    const int base = tid * SEG;
    unsigned keys[SEG];
    if (base + SEG <= G) {
#pragma unroll
        for (int i = 0; i < SEG; i += 4) {
            float4 v = *(const float4*)(&row[base + i]);
            keys[i + 0] = __float_as_uint(v.x);
            keys[i + 1] = __float_as_uint(v.y);
            keys[i + 2] = __float_as_uint(v.z);
            keys[i + 3] = __float_as_uint(v.w);
        }
    } else {
#pragma unroll
        for (int i = 0; i < SEG; ++i)
            keys[i] = (base + i < G) ? __float_as_uint(row[base + i]) : 0u;
    }

    if (tid == 0) { s_prefix = 0u; s_remaining = K; }
    __syncthreads();

#pragma unroll
    for (int pass = 0; pass < 4; ++pass) {
        const int shift = 24 - 8 * pass;
        const unsigned maskHigh = (pass == 0) ? 0u : (0xFFFFFFFFu << (shift + 8));
        if (tid < 256) hist[tid] = 0u;
        __syncthreads();
        const unsigned prefix = s_prefix;
        const int rem = s_remaining;
#pragma unroll
        for (int i = 0; i < SEG; ++i) {
            unsigned key = keys[i];
            if ((key & maskHigh) == prefix)
                atomicAdd(&hist[(key >> shift) & 0xFFu], 1u);
        }
        __syncthreads();
        int v = (tid < 256) ? (int)hist[255 - tid] : 0;
        int excl, total;
        block_scan(v, excl, total);
        int incl = excl + v;
        if (tid < 256 && incl >= rem && excl < rem) {
            s_prefix    = prefix | ((unsigned)(255 - tid) << shift);
            s_remaining = rem - excl;
        }
        __syncthreads();
    }
    const unsigned pivot = s_prefix;
    const int r = s_remaining;

    int n_gt = 0, n_eq = 0;
#pragma unroll
    for (int i = 0; i < SEG; ++i) {
        n_gt += (keys[i] > pivot);
        n_eq += (keys[i] == pivot);
    }
    int eq_base, eq_tot;
    block_scan(n_eq, eq_base, eq_tot);
    int eq_keep = 0;
    if (pivot > 0u) {
        int take = r - eq_base;
        eq_keep = take < 0 ? 0 : (take > n_eq ? n_eq : take);
    }
    int n_keep = n_gt + eq_keep;
    int out_base, out_tot;
    block_scan(n_keep, out_base, out_tot);

    int pos = out_base, erank = eq_base;
    int2* __restrict__ sel = g_selv + b * MAXK;
#pragma unroll
    for (int i = 0; i < SEG; ++i) {
        unsigned key = keys[i];
        if (key > pivot) {
            sel[pos++] = make_int2(base + i, (int)key);
        } else if (key == pivot) {
            if (pivot > 0u && erank < r) sel[pos++] = make_int2(base + i, (int)key);
            ++erank;
        }
    }
    const int cnt = (out_tot < K) ? out_tot : K;
    if (tid == 0) g_cnt[b] = cnt;

    // ---- fused cls row + mask epilogue ----
    const size_t rowsz = (size_t)(K + 1) * D_DIM;
    float* orow = out + (size_t)b * rowsz;
    if (tid < D_DIM) orow[tid] = cls[tid];
    if (hasMask) {
        float* mask = out + (size_t)B * rowsz + (size_t)b * (K + 1);
        for (int j = tid; j < K + 1; j += TOPK_NT)
            mask[j] = (j == 0 || (j - 1) < cnt) ? 1.0f : 0.0f;
    }
}

// ================= interp/gather kernel (warp-per-token) =================
// 256 threads = 8 warps = 8 tokens per block. Each lane: 2 float4 of the row.
__global__ __launch_bounds__(256)
void interp_kernel(const float* __restrict__ gene_emb,
                   float* __restrict__ out,
                   int B, int G, int K) {
    const int wid  = threadIdx.x >> 5;
    const int lane = threadIdx.x & 31;
    const int tkn  = blockIdx.x * 8 + wid;
    const int b = tkn / K, k = tkn - b * K;

    int gi = 0, xb = 0, cnt = 0;
    if (lane == 0) {
        cnt = g_cnt[b];
        int2 gv = g_selv[b * MAXK + k];
        gi = gv.x; xb = gv.y;
    }
    cnt = __shfl_sync(0xFFFFFFFFu, cnt, 0);
    gi  = __shfl_sync(0xFFFFFFFFu, gi, 0);
    xb  = __shfl_sync(0xFFFFFFFFu, xb, 0);

    const size_t rowoff = ((size_t)b * (K + 1) + (k + 1)) * D_DIM;
    float4* __restrict__ orow = (float4*)(out + rowoff);

    if (k < cnt) {
        float x = __int_as_float(xb);
        float u = x * (float)(TBL - 1);
        int i0 = (int)u;
        if (i0 < 0) i0 = 0;
        if (i0 > TBL - 2) i0 = TBL - 2;
        float f = u - (float)i0;

        const float4* __restrict__ T0 = (const float4*)(&g_tbl[(size_t)i0 * D_DIM]);
        const float4* __restrict__ T1 = (const float4*)(&g_tbl[(size_t)(i0 + 1) * D_DIM]);
        const float4* __restrict__ GE = (const float4*)(&gene_emb[(size_t)gi * D_DIM]);

        // issue all 6 loads before consuming (MLP=6)
        float4 t0a = T0[lane],      t0b = T0[lane + 32];
        float4 t1a = T1[lane],      t1b = T1[lane + 32];
        float4 gea = GE[lane],      geb = GE[lane + 32];

        float4 va, vb;
        va.x = fmaf(t1a.x - t0a.x, f, t0a.x) + gea.x;
        va.y = fmaf(t1a.y - t0a.y, f, t0a.y) + gea.y;
        va.z = fmaf(t1a.z - t0a.z, f, t0a.z) + gea.z;
        va.w = fmaf(t1a.w - t0a.w, f, t0a.w) + gea.w;
        vb.x = fmaf(t1b.x - t0b.x, f, t0b.x) + geb.x;
        vb.y = fmaf(t1b.y - t0b.y, f, t0b.y) + geb.y;
        vb.z = fmaf(t1b.z - t0b.z, f, t0b.z) + geb.z;
        vb.w = fmaf(t1b.w - t0b.w, f, t0b.w) + geb.w;
        __stcs(&orow[lane], va);
        __stcs(&orow[lane + 32], vb);
    } else {
        float4 z = make_float4(0.f, 0.f, 0.f, 0.f);
        __stcs(&orow[lane], z);
        __stcs(&orow[lane + 32], z);
    }
}

extern "C" void kernel_launch(void* const* d_in, const int* in_sizes, int n_in,
                              void* d_out, int out_size) {
    const float* expr     = (const float*)d_in[0];
    const float* gene_emb = (const float*)d_in[1];
    const float* w1       = (const float*)d_in[2];
    const float* b1       = (const float*)d_in[3];
    const float* w2       = (const float*)d_in[4];
    const float* b2       = (const float*)d_in[5];
    const float* cls      = (const float*)d_in[6];
    float* out = (float*)d_out;

    const int D = in_sizes[2];              // 256
    const int G = in_sizes[1] / D;          // 20000
    const int B = in_sizes[0] / G;          // 16

    long Kp1; int hasMask;
    if (out_size % ((long)B * (D + 1)) == 0) {
        Kp1 = out_size / ((long)B * (D + 1));
        hasMask = 1;
    } else {
        Kp1 = out_size / ((long)B * D);
        hasMask = 0;
    }
    const int K = (int)Kp1 - 1;             // 2048
    if (B > MAXB || K > MAXK || D != D_DIM) return;
    if (TOPK_NT * SEG < G) return;
    if ((B * K) % 8 != 0) return;

    cudaFuncSetAttribute(fused_kernel,
                         cudaFuncAttributeMaxDynamicSharedMemorySize, DYN_BYTES);

    fused_kernel<<<B + TGM_BLOCKS, TOPK_NT, DYN_BYTES>>>(
        expr, w1, b1, w2, b2, cls, out, B, G, K, hasMask);

    interp_kernel<<<(B * K) / 8, 256>>>(gene_emb, out, B, G, K);
}